// round 6
// baseline (speedup 1.0000x reference)
#include <cuda_runtime.h>
#include <cstdint>

// LengthTransform, round 6 (= round 5 re-bench after infra failure):
// prefetch-before-softmax, all-ones mask fast flag, interleaved softmax
// reductions, wide prep, 2 t's/warp float4 half-split.

#define TT       16    // t-values per block (8 warps x 2 t)
#define NTH_B    256
#define NROWS    36    // union window rows (32 + delta, delta<=4)
#define NPAIRS   18
#define CHUNK    6

__device__ float4 g_params[1024];   // {r, i2, tl_f, allones} per batch

__global__ __launch_bounds__(512)
void lt_prep(const float* __restrict__ mask,
             const float* __restrict__ ls_ptr,
             const int*   __restrict__ tgt_lens,
             int B, int S)
{
    const int b    = blockIdx.x;
    const int tid  = threadIdx.x;
    const int lane = tid & 31;
    const int wid  = tid >> 5;
    __shared__ float rsum[16], rmn[16], rmx[16];

    float part = 0.f, mn = 3.0e38f, mx = -3.0e38f;
    const int S4 = S >> 2;
    const float4* m4 = (const float4*)(mask + (size_t)b * S);
    for (int i = tid; i < S4; i += 512) {
        float4 v = m4[i];
        part += (v.x + v.y) + (v.z + v.w);
        mn = fminf(mn, fminf(fminf(v.x, v.y), fminf(v.z, v.w)));
        mx = fmaxf(mx, fmaxf(fmaxf(v.x, v.y), fmaxf(v.z, v.w)));
    }
    for (int i = (S4 << 2) + tid; i < S; i += 512) {
        float v = mask[(size_t)b * S + i];
        part += v; mn = fminf(mn, v); mx = fmaxf(mx, v);
    }
    #pragma unroll
    for (int o = 16; o > 0; o >>= 1) {
        part += __shfl_xor_sync(0xffffffffu, part, o);
        mn = fminf(mn, __shfl_xor_sync(0xffffffffu, mn, o));
        mx = fmaxf(mx, __shfl_xor_sync(0xffffffffu, mx, o));
    }
    if (lane == 0) { rsum[wid] = part; rmn[wid] = mn; rmx[wid] = mx; }
    __syncthreads();
    if (tid == 0) {
        float sl = 0.f, amn = 3.0e38f, amx = -3.0e38f;
        #pragma unroll
        for (int i = 0; i < 16; i++) {
            sl += rsum[i];
            amn = fminf(amn, rmn[i]);
            amx = fmaxf(amx, rmx[i]);
        }
        int   tl = tgt_lens[b];
        float ls = ls_ptr[0];
        float ao = (amn == 1.0f && amx == 1.0f) ? 1.0f : 0.0f;
        g_params[b] = make_float4(sl / (float)tl, 1.0f / (2.0f * ls * ls), (float)tl, ao);
    }
}

__global__ __launch_bounds__(NTH_B, 4)
void lt_main(const float* __restrict__ x,      // (B,S,64)
             const float* __restrict__ mask,   // (B,S)
             float* __restrict__ out_feat,     // (B,T,64)
             float* __restrict__ out_mask,     // (B,T) or null
             int B, int S, int T)
{
    const int b    = blockIdx.y;
    const int t0   = blockIdx.x * TT;
    const int tid  = threadIdx.x;
    const int lane = tid & 31;
    const int wid  = tid >> 5;
    const int tg   = wid * 2;
    const int h    = lane >> 4;          // half-warp (row parity)

    __shared__ float wpad[TT][64];       // per-t weights, 16-padded both sides

    const float4 p  = g_params[b];
    const float  r  = p.x;
    const float  i2 = p.y;
    const int    tl = (int)p.z;
    const bool   allones = (p.w != 0.0f);

    // zero this warp's 2 padded weight rows
    {
        float4* wz = (float4*)&wpad[tg][0];
        wz[lane] = make_float4(0.f, 0.f, 0.f, 0.f);
    }
    if (out_mask && lane < 2) {
        int t = t0 + tg + lane;
        if (t < T) out_mask[(size_t)b * T + t] = (t < tl) ? 1.0f : 0.0f;
    }

    // ---- window bases (pure ALU, no deps on memory) ----
    const int   ta  = min(t0 + tg, T - 1);
    const int   tb  = min(t0 + tg + 1, T - 1);
    const float c0  = r * (float)ta;
    const float c1  = r * (float)tb;
    const int   s00 = __float2int_rn(c0);
    const int   s01 = __float2int_rn(c1);
    const int   sb0 = min(max(s00 - 15, 0), S - 32);
    const int   sb1 = min(max(s01 - 15, 0), S - 32);
    const int   delta = sb1 - sb0;
    const bool  fast  = (delta >= 0) && (delta <= 4) && (sb0 + NROWS <= S);

    const float4* __restrict__ xr4 = (const float4*)(x + ((size_t)b * S + sb0) * 64);

    // ---- prefetch chunk0 of x BEFORE softmax (independent of weights) ----
    float4 buf[2][CHUNK];
    if (fast) {
        #pragma unroll
        for (int k = 0; k < CHUNK; k++) buf[0][k] = xr4[k * 32 + lane];
    }

    // ---- windowed softmax for both t's, interleaved, analytic max ----
    {
        float mv0 = 1.0f, mv1 = 1.0f;
        if (!allones) {
            mv0 = mask[(size_t)b * S + sb0 + lane];
            mv1 = mask[(size_t)b * S + sb1 + lane];
        }
        const int   sn0 = min(max(s00, 0), S - 1);
        const int   sn1 = min(max(s01, 0), S - 1);
        const float dm0 = (float)sn0 - c0;
        const float dm1 = (float)sn1 - c1;
        const float M0  = -dm0 * dm0 * i2;
        const float M1  = -dm1 * dm1 * i2;
        const float d0  = (float)(sb0 + lane) - c0;
        const float d1  = (float)(sb1 + lane) - c1;
        float lg0, lg1;
        if (allones) {
            lg0 = -d0 * d0 * i2;
            lg1 = -d1 * d1 * i2;
        } else {
            lg0 = mv0 * (-d0 * d0 * i2) - (1.0f - mv0) * 1e10f;
            lg1 = mv1 * (-d1 * d1 * i2) - (1.0f - mv1) * 1e10f;
        }
        float e0 = __expf(lg0 - M0);
        float e1 = __expf(lg1 - M1);
        float sm0 = e0, sm1 = e1;
        #pragma unroll
        for (int o = 16; o > 0; o >>= 1) {
            sm0 += __shfl_xor_sync(0xffffffffu, sm0, o);
            sm1 += __shfl_xor_sync(0xffffffffu, sm1, o);
        }
        wpad[tg + 0][16 + lane] = e0 * __fdividef(1.0f, sm0);
        wpad[tg + 1][16 + lane] = e1 * __fdividef(1.0f, sm1);
    }
    __syncwarp();

    float4 a0 = {0.f, 0.f, 0.f, 0.f};
    float4 a1 = {0.f, 0.f, 0.f, 0.f};

    if (fast) {
        // lane covers row 2*pair+h, D-chunk (lane&15); 3 chunks of 6 pairs
        const float* __restrict__ w0p = &wpad[tg + 0][16 + h];            // ub==sb0
        const float* __restrict__ w1p = &wpad[tg + 1][16 - delta + h];
        #pragma unroll
        for (int c = 0; c < NPAIRS / CHUNK; c++) {
            if (c + 1 < NPAIRS / CHUNK) {
                #pragma unroll
                for (int k = 0; k < CHUNK; k++)
                    buf[(c + 1) & 1][k] = xr4[((c + 1) * CHUNK + k) * 32 + lane];
            }
            #pragma unroll
            for (int k = 0; k < CHUNK; k++) {
                int   j  = (c * CHUNK + k) * 2;
                float w0 = w0p[j];
                float w1 = w1p[j];
                float4 xv = buf[c & 1][k];
                a0.x = fmaf(w0, xv.x, a0.x);  a0.y = fmaf(w0, xv.y, a0.y);
                a0.z = fmaf(w0, xv.z, a0.z);  a0.w = fmaf(w0, xv.w, a0.w);
                a1.x = fmaf(w1, xv.x, a1.x);  a1.y = fmaf(w1, xv.y, a1.y);
                a1.z = fmaf(w1, xv.z, a1.z);  a1.w = fmaf(w1, xv.w, a1.w);
            }
        }
    } else {
        // boundary path: per-t independent 32-row sweep (16 pairs)
        const int sbs[2] = {sb0, sb1};
        #pragma unroll
        for (int tt = 0; tt < 2; tt++) {
            const float4* xt4 = (const float4*)(x + ((size_t)b * S + sbs[tt]) * 64);
            const float*  wp  = &wpad[tg + tt][16 + h];
            float4 acc = {0.f, 0.f, 0.f, 0.f};
            #pragma unroll 4
            for (int pr = 0; pr < 16; pr++) {
                float4 xv = xt4[pr * 32 + lane];
                float  w  = wp[pr * 2];
                acc.x = fmaf(w, xv.x, acc.x);  acc.y = fmaf(w, xv.y, acc.y);
                acc.z = fmaf(w, xv.z, acc.z);  acc.w = fmaf(w, xv.w, acc.w);
            }
            if (tt == 0) a0 = acc; else a1 = acc;
        }
    }

    // combine row-halves (butterfly leaves sum in both halves)
    a0.x += __shfl_xor_sync(0xffffffffu, a0.x, 16);
    a0.y += __shfl_xor_sync(0xffffffffu, a0.y, 16);
    a0.z += __shfl_xor_sync(0xffffffffu, a0.z, 16);
    a0.w += __shfl_xor_sync(0xffffffffu, a0.w, 16);
    a1.x += __shfl_xor_sync(0xffffffffu, a1.x, 16);
    a1.y += __shfl_xor_sync(0xffffffffu, a1.y, 16);
    a1.z += __shfl_xor_sync(0xffffffffu, a1.z, 16);
    a1.w += __shfl_xor_sync(0xffffffffu, a1.w, 16);

    // lanes 0-15 store t (tg+0), lanes 16-31 store t (tg+1): one STG.128
    int    tsel = t0 + tg + h;
    float4 av   = h ? a1 : a0;
    if (tsel < T) {
        float4* o4 = (float4*)(out_feat + ((size_t)b * T + tsel) * 64);
        o4[lane & 15] = av;
    }
}

// Generic fallback (any D, any S>=32): one warp per (b,t).
__global__ void length_transform_generic(const float* __restrict__ x,
                                         const float* __restrict__ mask,
                                         const float* __restrict__ ls_ptr,
                                         const int*   __restrict__ tgt_lens,
                                         float* __restrict__ out_feat,
                                         float* __restrict__ out_mask,
                                         int B, int S, int T, int D)
{
    int bt = blockIdx.x;
    int b = bt / T, t = bt % T;
    int lane = threadIdx.x;
    __shared__ float wsh[32];

    float part = 0.f;
    for (int i = lane; i < S; i += 32) part += mask[(size_t)b * S + i];
    #pragma unroll
    for (int o = 16; o > 0; o >>= 1) part += __shfl_xor_sync(0xffffffffu, part, o);
    float sl = part;
    int   tl = tgt_lens[b];
    float r  = sl / (float)tl;
    float ls = ls_ptr[0];
    float i2 = 1.f / (2.f * ls * ls);

    float c  = r * (float)t;
    int   s0 = __float2int_rn(c);
    int   sb = min(max(s0 - 15, 0), max(S - 32, 0));
    int   s  = min(sb + lane, S - 1);
    float d  = (float)s - c;
    float lg0 = -d * d * i2;
    float m  = mask[(size_t)b * S + s];
    float lg = m * lg0 - (1.f - m) * 1e10f;
    if (sb + lane > S - 1) lg = -3.0e38f;
    float mx = lg;
    #pragma unroll
    for (int o = 16; o > 0; o >>= 1) mx = fmaxf(mx, __shfl_xor_sync(0xffffffffu, mx, o));
    float e = __expf(lg - mx);
    float sm = e;
    #pragma unroll
    for (int o = 16; o > 0; o >>= 1) sm += __shfl_xor_sync(0xffffffffu, sm, o);
    wsh[lane] = e / sm;
    __syncwarp();

    for (int dd = lane; dd < D; dd += 32) {
        float acc = 0.f;
        for (int k = 0; k < 32; k++) {
            int ss = sb + k;
            if (ss >= S) break;
            acc = fmaf(wsh[k], x[((size_t)b * S + ss) * D + dd], acc);
        }
        out_feat[((size_t)b * T + t) * D + dd] = acc;
    }
    if (out_mask && lane == 0) out_mask[(size_t)b * T + t] = (t < tl) ? 1.f : 0.f;
}

extern "C" void kernel_launch(void* const* d_in, const int* in_sizes, int n_in,
                              void* d_out, int out_size)
{
    const float* x     = (const float*)d_in[0];
    const float* mask  = (const float*)d_in[1];
    const float* ls    = (const float*)d_in[2];
    const int*   tlens = (const int*)d_in[3];

    const int BSD = in_sizes[0];
    const int BS  = in_sizes[1];
    const int B   = in_sizes[3];
    const int D   = BSD / BS;
    const int S   = BS / B;

    long fp1 = (long)B * (D + 1);
    int  T;
    bool has_mask;
    if (out_size % fp1 == 0) { T = (int)(out_size / fp1); has_mask = true; }
    else                     { T = (int)(out_size / ((long)B * D)); has_mask = false; }

    float* ofeat = (float*)d_out;
    float* omask = has_mask ? ofeat + (size_t)B * T * D : nullptr;

    if (D == 64 && S >= 64 && B <= 1024) {
        lt_prep<<<B, 512>>>(mask, ls, tlens, B, S);
        dim3 grid((T + TT - 1) / TT, B);
        lt_main<<<grid, NTH_B>>>(x, mask, ofeat, omask, B, S, T);
    } else {
        length_transform_generic<<<B * T, 32>>>(x, mask, ls, tlens, ofeat, omask, B, S, T, D);
    }
}

// round 7
// speedup vs baseline: 1.0200x; 1.0200x over previous
#include <cuda_runtime.h>
#include <cstdint>

// LengthTransform, round 7: block-level SMEM staging of the union row window.
// Stage 84 rows of x into smem with batched LDG.128 (overlapped with softmax),
// then the per-warp 18-pair FMA loop reads LDS instead of L2.

#define TT       16    // t-values per block (8 warps x 2 t)
#define NTH_B    256
#define NROWS    36    // per-warp union rows (32 + delta, delta<=4)
#define NPAIRS   18
#define SROWS    84    // staged rows per block (covers r <= 3.2 + padding)
#define SVEC     (SROWS * 16)   // float4 count = 1344

__device__ float4 g_params[1024];   // {r, i2, tl_f, allones} per batch

__global__ __launch_bounds__(512)
void lt_prep(const float* __restrict__ mask,
             const float* __restrict__ ls_ptr,
             const int*   __restrict__ tgt_lens,
             int B, int S)
{
    const int b    = blockIdx.x;
    const int tid  = threadIdx.x;
    const int lane = tid & 31;
    const int wid  = tid >> 5;
    __shared__ float rsum[16], rmn[16], rmx[16];

    float part = 0.f, mn = 3.0e38f, mx = -3.0e38f;
    const int S4 = S >> 2;
    const float4* m4 = (const float4*)(mask + (size_t)b * S);
    for (int i = tid; i < S4; i += 512) {
        float4 v = m4[i];
        part += (v.x + v.y) + (v.z + v.w);
        mn = fminf(mn, fminf(fminf(v.x, v.y), fminf(v.z, v.w)));
        mx = fmaxf(mx, fmaxf(fmaxf(v.x, v.y), fmaxf(v.z, v.w)));
    }
    for (int i = (S4 << 2) + tid; i < S; i += 512) {
        float v = mask[(size_t)b * S + i];
        part += v; mn = fminf(mn, v); mx = fmaxf(mx, v);
    }
    #pragma unroll
    for (int o = 16; o > 0; o >>= 1) {
        part += __shfl_xor_sync(0xffffffffu, part, o);
        mn = fminf(mn, __shfl_xor_sync(0xffffffffu, mn, o));
        mx = fmaxf(mx, __shfl_xor_sync(0xffffffffu, mx, o));
    }
    if (lane == 0) { rsum[wid] = part; rmn[wid] = mn; rmx[wid] = mx; }
    __syncthreads();
    if (tid == 0) {
        float sl = 0.f, amn = 3.0e38f, amx = -3.0e38f;
        #pragma unroll
        for (int i = 0; i < 16; i++) {
            sl += rsum[i];
            amn = fminf(amn, rmn[i]);
            amx = fmaxf(amx, rmx[i]);
        }
        int   tl = tgt_lens[b];
        float ls = ls_ptr[0];
        float ao = (amn == 1.0f && amx == 1.0f) ? 1.0f : 0.0f;
        g_params[b] = make_float4(sl / (float)tl, 1.0f / (2.0f * ls * ls), (float)tl, ao);
    }
}

__global__ __launch_bounds__(NTH_B, 4)
void lt_main(const float* __restrict__ x,      // (B,S,64)
             const float* __restrict__ mask,   // (B,S)
             float* __restrict__ out_feat,     // (B,T,64)
             float* __restrict__ out_mask,     // (B,T) or null
             int B, int S, int T)
{
    const int b    = blockIdx.y;
    const int t0   = blockIdx.x * TT;
    const int tid  = threadIdx.x;
    const int lane = tid & 31;
    const int wid  = tid >> 5;
    const int tg   = wid * 2;
    const int h    = lane >> 4;          // half-warp (row parity)

    __shared__ float wpad[TT][64];       // per-t weights, 16-padded both sides
    __shared__ float xs[SROWS * 64];     // staged x rows (21 KB)

    const float4 p  = g_params[b];
    const float  r  = p.x;
    const float  i2 = p.y;
    const int    tl = (int)p.z;
    const bool   allones = (p.w != 0.0f);

    // ---- block-uniform stage window ----
    const int   tF  = min(t0, T - 1);
    const int   tL  = min(t0 + TT - 1, T - 1);
    const int   sbF = min(max(__float2int_rn(r * (float)tF) - 15, 0), S - 32);
    const int   sbL = min(max(__float2int_rn(r * (float)tL) - 15, 0), S - 32);
    const int   st0 = sbF;
    const bool  blockfast = (sbL - sbF >= 0) && (sbL - sbF <= SROWS - NROWS);

    // ---- per-warp window bases ----
    const int   ta  = min(t0 + tg, T - 1);
    const int   tb  = min(t0 + tg + 1, T - 1);
    const float c0  = r * (float)ta;
    const float c1  = r * (float)tb;
    const int   s00 = __float2int_rn(c0);
    const int   s01 = __float2int_rn(c1);
    const int   sb0 = min(max(s00 - 15, 0), S - 32);
    const int   sb1 = min(max(s01 - 15, 0), S - 32);
    const int   delta = sb1 - sb0;

    // ---- stage loads into registers (MLP=6, issued before softmax) ----
    float4 sreg[6];
    const float4* __restrict__ xg4 = (const float4*)(x + ((size_t)b * S + st0) * 64);
    if (blockfast) {
        #pragma unroll
        for (int k = 0; k < 6; k++) {
            int idx = tid + k * NTH_B;
            int row = idx >> 4;
            sreg[k] = (idx < SVEC && st0 + row < S) ? xg4[idx]
                                                    : make_float4(0.f, 0.f, 0.f, 0.f);
        }
    }

    // ---- zero this warp's 2 padded weight rows ----
    {
        float4* wz = (float4*)&wpad[tg][0];
        wz[lane] = make_float4(0.f, 0.f, 0.f, 0.f);
    }
    if (out_mask && lane < 2) {
        int t = t0 + tg + lane;
        if (t < T) out_mask[(size_t)b * T + t] = (t < tl) ? 1.0f : 0.0f;
    }
    __syncwarp();

    // ---- windowed softmax for both t's, interleaved, analytic max ----
    {
        float mv0 = 1.0f, mv1 = 1.0f;
        if (!allones) {
            mv0 = mask[(size_t)b * S + sb0 + lane];
            mv1 = mask[(size_t)b * S + sb1 + lane];
        }
        const int   sn0 = min(max(s00, 0), S - 1);
        const int   sn1 = min(max(s01, 0), S - 1);
        const float dm0 = (float)sn0 - c0;
        const float dm1 = (float)sn1 - c1;
        const float M0  = -dm0 * dm0 * i2;
        const float M1  = -dm1 * dm1 * i2;
        const float d0  = (float)(sb0 + lane) - c0;
        const float d1  = (float)(sb1 + lane) - c1;
        float lg0, lg1;
        if (allones) {
            lg0 = -d0 * d0 * i2;
            lg1 = -d1 * d1 * i2;
        } else {
            lg0 = mv0 * (-d0 * d0 * i2) - (1.0f - mv0) * 1e10f;
            lg1 = mv1 * (-d1 * d1 * i2) - (1.0f - mv1) * 1e10f;
        }
        float e0 = __expf(lg0 - M0);
        float e1 = __expf(lg1 - M1);
        float sm0 = e0, sm1 = e1;
        #pragma unroll
        for (int o = 16; o > 0; o >>= 1) {
            sm0 += __shfl_xor_sync(0xffffffffu, sm0, o);
            sm1 += __shfl_xor_sync(0xffffffffu, sm1, o);
        }
        wpad[tg + 0][16 + lane] = e0 * __fdividef(1.0f, sm0);
        wpad[tg + 1][16 + lane] = e1 * __fdividef(1.0f, sm1);
    }

    // ---- drain stage registers into smem, then one barrier ----
    if (blockfast) {
        float4* xs4 = (float4*)xs;
        #pragma unroll
        for (int k = 0; k < 6; k++) {
            int idx = tid + k * NTH_B;
            if (idx < SVEC) xs4[idx] = sreg[k];
        }
    }
    __syncthreads();

    float4 a0 = {0.f, 0.f, 0.f, 0.f};
    float4 a1 = {0.f, 0.f, 0.f, 0.f};

    if (blockfast && delta >= 0 && delta <= 4) {
        // inner loop entirely from smem: lane covers row 2k+h, chunk lane&15
        const float4* __restrict__ xw4 = ((const float4*)xs) + (sb0 - st0) * 16;
        const float*  __restrict__ w0p = &wpad[tg + 0][16 + h];
        const float*  __restrict__ w1p = &wpad[tg + 1][16 - delta + h];
        #pragma unroll
        for (int k = 0; k < NPAIRS; k++) {
            float4 xv = xw4[k * 32 + lane];
            float  w0 = w0p[2 * k];
            float  w1 = w1p[2 * k];
            a0.x = fmaf(w0, xv.x, a0.x);  a0.y = fmaf(w0, xv.y, a0.y);
            a0.z = fmaf(w0, xv.z, a0.z);  a0.w = fmaf(w0, xv.w, a0.w);
            a1.x = fmaf(w1, xv.x, a1.x);  a1.y = fmaf(w1, xv.y, a1.y);
            a1.z = fmaf(w1, xv.z, a1.z);  a1.w = fmaf(w1, xv.w, a1.w);
        }
    } else {
        // exotic-r path: per-t independent 32-row sweep from global
        const int sbs[2] = {sb0, sb1};
        #pragma unroll
        for (int tt = 0; tt < 2; tt++) {
            const float4* xt4 = (const float4*)(x + ((size_t)b * S + sbs[tt]) * 64);
            const float*  wp  = &wpad[tg + tt][16 + h];
            float4 acc = {0.f, 0.f, 0.f, 0.f};
            #pragma unroll 4
            for (int pr = 0; pr < 16; pr++) {
                float4 xv = xt4[pr * 32 + lane];
                float  w  = wp[pr * 2];
                acc.x = fmaf(w, xv.x, acc.x);  acc.y = fmaf(w, xv.y, acc.y);
                acc.z = fmaf(w, xv.z, acc.z);  acc.w = fmaf(w, xv.w, acc.w);
            }
            if (tt == 0) a0 = acc; else a1 = acc;
        }
    }

    // combine row-halves (butterfly leaves sum in both halves)
    a0.x += __shfl_xor_sync(0xffffffffu, a0.x, 16);
    a0.y += __shfl_xor_sync(0xffffffffu, a0.y, 16);
    a0.z += __shfl_xor_sync(0xffffffffu, a0.z, 16);
    a0.w += __shfl_xor_sync(0xffffffffu, a0.w, 16);
    a1.x += __shfl_xor_sync(0xffffffffu, a1.x, 16);
    a1.y += __shfl_xor_sync(0xffffffffu, a1.y, 16);
    a1.z += __shfl_xor_sync(0xffffffffu, a1.z, 16);
    a1.w += __shfl_xor_sync(0xffffffffu, a1.w, 16);

    // lanes 0-15 store t (tg+0), lanes 16-31 store t (tg+1): one STG.128
    int    tsel = t0 + tg + h;
    float4 av   = h ? a1 : a0;
    if (tsel < T) {
        float4* o4 = (float4*)(out_feat + ((size_t)b * T + tsel) * 64);
        o4[lane & 15] = av;
    }
}

// Generic fallback (any D, any S>=32): one warp per (b,t).
__global__ void length_transform_generic(const float* __restrict__ x,
                                         const float* __restrict__ mask,
                                         const float* __restrict__ ls_ptr,
                                         const int*   __restrict__ tgt_lens,
                                         float* __restrict__ out_feat,
                                         float* __restrict__ out_mask,
                                         int B, int S, int T, int D)
{
    int bt = blockIdx.x;
    int b = bt / T, t = bt % T;
    int lane = threadIdx.x;
    __shared__ float wsh[32];

    float part = 0.f;
    for (int i = lane; i < S; i += 32) part += mask[(size_t)b * S + i];
    #pragma unroll
    for (int o = 16; o > 0; o >>= 1) part += __shfl_xor_sync(0xffffffffu, part, o);
    float sl = part;
    int   tl = tgt_lens[b];
    float r  = sl / (float)tl;
    float ls = ls_ptr[0];
    float i2 = 1.f / (2.f * ls * ls);

    float c  = r * (float)t;
    int   s0 = __float2int_rn(c);
    int   sb = min(max(s0 - 15, 0), max(S - 32, 0));
    int   s  = min(sb + lane, S - 1);
    float d  = (float)s - c;
    float lg0 = -d * d * i2;
    float m  = mask[(size_t)b * S + s];
    float lg = m * lg0 - (1.f - m) * 1e10f;
    if (sb + lane > S - 1) lg = -3.0e38f;
    float mx = lg;
    #pragma unroll
    for (int o = 16; o > 0; o >>= 1) mx = fmaxf(mx, __shfl_xor_sync(0xffffffffu, mx, o));
    float e = __expf(lg - mx);
    float sm = e;
    #pragma unroll
    for (int o = 16; o > 0; o >>= 1) sm += __shfl_xor_sync(0xffffffffu, sm, o);
    wsh[lane] = e / sm;
    __syncwarp();

    for (int dd = lane; dd < D; dd += 32) {
        float acc = 0.f;
        for (int k = 0; k < 32; k++) {
            int ss = sb + k;
            if (ss >= S) break;
            acc = fmaf(wsh[k], x[((size_t)b * S + ss) * D + dd], acc);
        }
        out_feat[((size_t)b * T + t) * D + dd] = acc;
    }
    if (out_mask && lane == 0) out_mask[(size_t)b * T + t] = (t < tl) ? 1.f : 0.f;
}

extern "C" void kernel_launch(void* const* d_in, const int* in_sizes, int n_in,
                              void* d_out, int out_size)
{
    const float* x     = (const float*)d_in[0];
    const float* mask  = (const float*)d_in[1];
    const float* ls    = (const float*)d_in[2];
    const int*   tlens = (const int*)d_in[3];

    const int BSD = in_sizes[0];
    const int BS  = in_sizes[1];
    const int B   = in_sizes[3];
    const int D   = BSD / BS;
    const int S   = BS / B;

    long fp1 = (long)B * (D + 1);
    int  T;
    bool has_mask;
    if (out_size % fp1 == 0) { T = (int)(out_size / fp1); has_mask = true; }
    else                     { T = (int)(out_size / ((long)B * D)); has_mask = false; }

    float* ofeat = (float*)d_out;
    float* omask = has_mask ? ofeat + (size_t)B * T * D : nullptr;

    if (D == 64 && S >= 64 && B <= 1024) {
        lt_prep<<<B, 512>>>(mask, ls, tlens, B, S);
        dim3 grid((T + TT - 1) / TT, B);
        lt_main<<<grid, NTH_B>>>(x, mask, ofeat, omask, B, S, T);
    } else {
        length_transform_generic<<<B * T, 32>>>(x, mask, ls, tlens, ofeat, omask, B, S, T, D);
    }
}

// round 8
// speedup vs baseline: 1.0226x; 1.0025x over previous
#include <cuda_runtime.h>
#include <cstdint>

// LengthTransform, round 8: cp.async (LDGSTS) smem staging — zero register
// footprint for the staged window, regs capped for 6 blocks/SM occupancy.
// tgt_mask moved to prep kernel.

#define TT       16    // t-values per block (8 warps x 2 t)
#define NTH_B    256
#define NROWS    36    // per-warp union rows (32 + delta, delta<=4)
#define NPAIRS   18
#define SROWS    84    // staged rows per block
#define SVEC     (SROWS * 16)   // float4 count = 1344

__device__ float4 g_params[1024];   // {r, i2, tl_f, allones} per batch

__device__ __forceinline__ void cp_async16(uint32_t saddr, const void* gptr, int src_bytes) {
    asm volatile("cp.async.cg.shared.global [%0], [%1], 16, %2;\n"
                 :: "r"(saddr), "l"(gptr), "r"(src_bytes));
}

__global__ __launch_bounds__(512)
void lt_prep(const float* __restrict__ mask,
             const float* __restrict__ ls_ptr,
             const int*   __restrict__ tgt_lens,
             float* __restrict__ out_mask,    // (B,T) or null
             int B, int S, int T)
{
    const int b    = blockIdx.x;
    const int tid  = threadIdx.x;
    const int lane = tid & 31;
    const int wid  = tid >> 5;
    __shared__ float rsum[16], rmn[16], rmx[16];

    const int tl = tgt_lens[b];

    // tgt_mask
    if (out_mask) {
        for (int t = tid; t < T; t += 512)
            out_mask[(size_t)b * T + t] = (t < tl) ? 1.0f : 0.0f;
    }

    float part = 0.f, mn = 3.0e38f, mx = -3.0e38f;
    const int S4 = S >> 2;
    const float4* m4 = (const float4*)(mask + (size_t)b * S);
    for (int i = tid; i < S4; i += 512) {
        float4 v = m4[i];
        part += (v.x + v.y) + (v.z + v.w);
        mn = fminf(mn, fminf(fminf(v.x, v.y), fminf(v.z, v.w)));
        mx = fmaxf(mx, fmaxf(fmaxf(v.x, v.y), fmaxf(v.z, v.w)));
    }
    for (int i = (S4 << 2) + tid; i < S; i += 512) {
        float v = mask[(size_t)b * S + i];
        part += v; mn = fminf(mn, v); mx = fmaxf(mx, v);
    }
    #pragma unroll
    for (int o = 16; o > 0; o >>= 1) {
        part += __shfl_xor_sync(0xffffffffu, part, o);
        mn = fminf(mn, __shfl_xor_sync(0xffffffffu, mn, o));
        mx = fmaxf(mx, __shfl_xor_sync(0xffffffffu, mx, o));
    }
    if (lane == 0) { rsum[wid] = part; rmn[wid] = mn; rmx[wid] = mx; }
    __syncthreads();
    if (tid == 0) {
        float sl = 0.f, amn = 3.0e38f, amx = -3.0e38f;
        #pragma unroll
        for (int i = 0; i < 16; i++) {
            sl += rsum[i];
            amn = fminf(amn, rmn[i]);
            amx = fmaxf(amx, rmx[i]);
        }
        float ls = ls_ptr[0];
        float ao = (amn == 1.0f && amx == 1.0f) ? 1.0f : 0.0f;
        g_params[b] = make_float4(sl / (float)tl, 1.0f / (2.0f * ls * ls), (float)tl, ao);
    }
}

__global__ __launch_bounds__(NTH_B, 6)
void lt_main(const float* __restrict__ x,      // (B,S,64)
             const float* __restrict__ mask,   // (B,S)
             float* __restrict__ out_feat,     // (B,T,64)
             int B, int S, int T)
{
    const int b    = blockIdx.y;
    const int t0   = blockIdx.x * TT;
    const int tid  = threadIdx.x;
    const int lane = tid & 31;
    const int wid  = tid >> 5;
    const int tg   = wid * 2;
    const int h    = lane >> 4;          // half-warp (row parity)

    __shared__ float wpad[TT][64];       // per-t weights, 16-padded both sides
    __shared__ float xs[SROWS * 64];     // staged x rows (21 KB)

    const float4 p  = g_params[b];
    const float  r  = p.x;
    const float  i2 = p.y;
    const bool   allones = (p.w != 0.0f);

    // ---- block-uniform stage window ----
    const int   tF  = min(t0, T - 1);
    const int   tL  = min(t0 + TT - 1, T - 1);
    const int   sbF = min(max(__float2int_rn(r * (float)tF) - 15, 0), S - 32);
    const int   sbL = min(max(__float2int_rn(r * (float)tL) - 15, 0), S - 32);
    const int   st0 = sbF;
    const bool  blockfast = (sbL - sbF >= 0) && (sbL - sbF <= SROWS - NROWS);

    // ---- per-warp window bases ----
    const int   ta  = min(t0 + tg, T - 1);
    const int   tb  = min(t0 + tg + 1, T - 1);
    const float c0  = r * (float)ta;
    const float c1  = r * (float)tb;
    const int   s00 = __float2int_rn(c0);
    const int   s01 = __float2int_rn(c1);
    const int   sb0 = min(max(s00 - 15, 0), S - 32);
    const int   sb1 = min(max(s01 - 15, 0), S - 32);
    const int   delta = sb1 - sb0;

    // ---- stage via cp.async: no registers held, overlapped with softmax ----
    if (blockfast) {
        const float4* xg4 = (const float4*)(x + ((size_t)b * S + st0) * 64);
        uint32_t xs_base = (uint32_t)__cvta_generic_to_shared(xs);
        const int avail = (S - st0) * 16;   // valid float4 count from st0
        #pragma unroll
        for (int k = 0; k < 6; k++) {
            int idx = tid + k * NTH_B;
            if (idx < SVEC) {
                int nb   = (idx < avail) ? 16 : 0;       // zero-fill rows >= S
                int gidx = min(idx, avail - 1);          // keep address in-bounds
                cp_async16(xs_base + (uint32_t)idx * 16u, xg4 + gidx, nb);
            }
        }
        asm volatile("cp.async.commit_group;\n" ::: "memory");
    }

    // ---- zero this warp's 2 padded weight rows ----
    {
        float4* wz = (float4*)&wpad[tg][0];
        wz[lane] = make_float4(0.f, 0.f, 0.f, 0.f);
    }
    __syncwarp();

    // ---- windowed softmax for both t's, interleaved, analytic max ----
    {
        float mv0 = 1.0f, mv1 = 1.0f;
        if (!allones) {
            mv0 = mask[(size_t)b * S + sb0 + lane];
            mv1 = mask[(size_t)b * S + sb1 + lane];
        }
        const int   sn0 = min(max(s00, 0), S - 1);
        const int   sn1 = min(max(s01, 0), S - 1);
        const float dm0 = (float)sn0 - c0;
        const float dm1 = (float)sn1 - c1;
        const float M0  = -dm0 * dm0 * i2;
        const float M1  = -dm1 * dm1 * i2;
        const float d0  = (float)(sb0 + lane) - c0;
        const float d1  = (float)(sb1 + lane) - c1;
        float lg0, lg1;
        if (allones) {
            lg0 = -d0 * d0 * i2;
            lg1 = -d1 * d1 * i2;
        } else {
            lg0 = mv0 * (-d0 * d0 * i2) - (1.0f - mv0) * 1e10f;
            lg1 = mv1 * (-d1 * d1 * i2) - (1.0f - mv1) * 1e10f;
        }
        float e0 = __expf(lg0 - M0);
        float e1 = __expf(lg1 - M1);
        float sm0 = e0, sm1 = e1;
        #pragma unroll
        for (int o = 16; o > 0; o >>= 1) {
            sm0 += __shfl_xor_sync(0xffffffffu, sm0, o);
            sm1 += __shfl_xor_sync(0xffffffffu, sm1, o);
        }
        wpad[tg + 0][16 + lane] = e0 * __fdividef(1.0f, sm0);
        wpad[tg + 1][16 + lane] = e1 * __fdividef(1.0f, sm1);
    }

    if (blockfast) asm volatile("cp.async.wait_group 0;\n" ::: "memory");
    __syncthreads();

    float4 a0 = {0.f, 0.f, 0.f, 0.f};
    float4 a1 = {0.f, 0.f, 0.f, 0.f};

    if (blockfast && delta >= 0 && delta <= 4) {
        // inner loop entirely from smem: lane covers row 2k+h, chunk lane&15
        const float4* __restrict__ xw4 = ((const float4*)xs) + (sb0 - st0) * 16;
        const float*  __restrict__ w0p = &wpad[tg + 0][16 + h];
        const float*  __restrict__ w1p = &wpad[tg + 1][16 - delta + h];
        #pragma unroll
        for (int k = 0; k < NPAIRS; k++) {
            float4 xv = xw4[k * 32 + lane];
            float  w0 = w0p[2 * k];
            float  w1 = w1p[2 * k];
            a0.x = fmaf(w0, xv.x, a0.x);  a0.y = fmaf(w0, xv.y, a0.y);
            a0.z = fmaf(w0, xv.z, a0.z);  a0.w = fmaf(w0, xv.w, a0.w);
            a1.x = fmaf(w1, xv.x, a1.x);  a1.y = fmaf(w1, xv.y, a1.y);
            a1.z = fmaf(w1, xv.z, a1.z);  a1.w = fmaf(w1, xv.w, a1.w);
        }
    } else {
        // exotic-r path: per-t independent 32-row sweep from global
        const int sbs[2] = {sb0, sb1};
        #pragma unroll
        for (int tt = 0; tt < 2; tt++) {
            const float4* xt4 = (const float4*)(x + ((size_t)b * S + sbs[tt]) * 64);
            const float*  wp  = &wpad[tg + tt][16 + h];
            float4 acc = {0.f, 0.f, 0.f, 0.f};
            #pragma unroll 4
            for (int pr = 0; pr < 16; pr++) {
                float4 xv = xt4[pr * 32 + lane];
                float  w  = wp[pr * 2];
                acc.x = fmaf(w, xv.x, acc.x);  acc.y = fmaf(w, xv.y, acc.y);
                acc.z = fmaf(w, xv.z, acc.z);  acc.w = fmaf(w, xv.w, acc.w);
            }
            if (tt == 0) a0 = acc; else a1 = acc;
        }
    }

    // combine row-halves (butterfly leaves sum in both halves)
    a0.x += __shfl_xor_sync(0xffffffffu, a0.x, 16);
    a0.y += __shfl_xor_sync(0xffffffffu, a0.y, 16);
    a0.z += __shfl_xor_sync(0xffffffffu, a0.z, 16);
    a0.w += __shfl_xor_sync(0xffffffffu, a0.w, 16);
    a1.x += __shfl_xor_sync(0xffffffffu, a1.x, 16);
    a1.y += __shfl_xor_sync(0xffffffffu, a1.y, 16);
    a1.z += __shfl_xor_sync(0xffffffffu, a1.z, 16);
    a1.w += __shfl_xor_sync(0xffffffffu, a1.w, 16);

    // lanes 0-15 store t (tg+0), lanes 16-31 store t (tg+1): one STG.128
    int    tsel = t0 + tg + h;
    float4 av   = h ? a1 : a0;
    if (tsel < T) {
        float4* o4 = (float4*)(out_feat + ((size_t)b * T + tsel) * 64);
        o4[lane & 15] = av;
    }
}

// Generic fallback (any D, any S>=32): one warp per (b,t).
__global__ void length_transform_generic(const float* __restrict__ x,
                                         const float* __restrict__ mask,
                                         const float* __restrict__ ls_ptr,
                                         const int*   __restrict__ tgt_lens,
                                         float* __restrict__ out_feat,
                                         float* __restrict__ out_mask,
                                         int B, int S, int T, int D)
{
    int bt = blockIdx.x;
    int b = bt / T, t = bt % T;
    int lane = threadIdx.x;
    __shared__ float wsh[32];

    float part = 0.f;
    for (int i = lane; i < S; i += 32) part += mask[(size_t)b * S + i];
    #pragma unroll
    for (int o = 16; o > 0; o >>= 1) part += __shfl_xor_sync(0xffffffffu, part, o);
    float sl = part;
    int   tl = tgt_lens[b];
    float r  = sl / (float)tl;
    float ls = ls_ptr[0];
    float i2 = 1.f / (2.f * ls * ls);

    float c  = r * (float)t;
    int   s0 = __float2int_rn(c);
    int   sb = min(max(s0 - 15, 0), max(S - 32, 0));
    int   s  = min(sb + lane, S - 1);
    float d  = (float)s - c;
    float lg0 = -d * d * i2;
    float m  = mask[(size_t)b * S + s];
    float lg = m * lg0 - (1.f - m) * 1e10f;
    if (sb + lane > S - 1) lg = -3.0e38f;
    float mx = lg;
    #pragma unroll
    for (int o = 16; o > 0; o >>= 1) mx = fmaxf(mx, __shfl_xor_sync(0xffffffffu, mx, o));
    float e = __expf(lg - mx);
    float sm = e;
    #pragma unroll
    for (int o = 16; o > 0; o >>= 1) sm += __shfl_xor_sync(0xffffffffu, sm, o);
    wsh[lane] = e / sm;
    __syncwarp();

    for (int dd = lane; dd < D; dd += 32) {
        float acc = 0.f;
        for (int k = 0; k < 32; k++) {
            int ss = sb + k;
            if (ss >= S) break;
            acc = fmaf(wsh[k], x[((size_t)b * S + ss) * D + dd], acc);
        }
        out_feat[((size_t)b * T + t) * D + dd] = acc;
    }
    if (out_mask && lane == 0) out_mask[(size_t)b * T + t] = (t < tl) ? 1.f : 0.f;
}

extern "C" void kernel_launch(void* const* d_in, const int* in_sizes, int n_in,
                              void* d_out, int out_size)
{
    const float* x     = (const float*)d_in[0];
    const float* mask  = (const float*)d_in[1];
    const float* ls    = (const float*)d_in[2];
    const int*   tlens = (const int*)d_in[3];

    const int BSD = in_sizes[0];
    const int BS  = in_sizes[1];
    const int B   = in_sizes[3];
    const int D   = BSD / BS;
    const int S   = BS / B;

    long fp1 = (long)B * (D + 1);
    int  T;
    bool has_mask;
    if (out_size % fp1 == 0) { T = (int)(out_size / fp1); has_mask = true; }
    else                     { T = (int)(out_size / ((long)B * D)); has_mask = false; }

    float* ofeat = (float*)d_out;
    float* omask = has_mask ? ofeat + (size_t)B * T * D : nullptr;

    if (D == 64 && S >= 64 && B <= 1024) {
        lt_prep<<<B, 512>>>(mask, ls, tlens, omask, B, S, T);
        dim3 grid((T + TT - 1) / TT, B);
        lt_main<<<grid, NTH_B>>>(x, mask, ofeat, B, S, T);
    } else {
        length_transform_generic<<<B * T, 32>>>(x, mask, ls, tlens, ofeat, omask, B, S, T, D);
    }
}

// round 9
// speedup vs baseline: 1.2179x; 1.1910x over previous
#include <cuda_runtime.h>
#include <cstdint>

// LengthTransform, round 9: single fused kernel. Per-block mask reduce
// (eliminates prep kernel + gap), 16-tap window (tail < 2e-14 of softmax
// mass), half-warp-per-t softmax, cp.async smem staging, 10-pair FMA loop.

#define TT       16    // t-values per block (8 warps x 2 t)
#define NTH_B    256
#define W        16    // softmax window taps per t
#define NPAIRS   10    // (W + delta_max)/2 = (16+4)/2
#define SROWS    56    // staged rows per block
#define SVEC     (SROWS * 16)   // 896 float4

__device__ __forceinline__ void cp_async16(uint32_t saddr, const void* gptr, int src_bytes) {
    asm volatile("cp.async.cg.shared.global [%0], [%1], 16, %2;\n"
                 :: "r"(saddr), "l"(gptr), "r"(src_bytes));
}

__global__ __launch_bounds__(NTH_B, 6)
void lt_fused(const float* __restrict__ x,      // (B,S,64)
              const float* __restrict__ mask,   // (B,S)
              const float* __restrict__ ls_ptr, // scalar
              const int*   __restrict__ tgt_lens,
              float* __restrict__ out_feat,     // (B,T,64)
              float* __restrict__ out_mask,     // (B,T) or null
              int B, int S, int T)
{
    const int b    = blockIdx.y;
    const int t0   = blockIdx.x * TT;
    const int tid  = threadIdx.x;
    const int lane = tid & 31;
    const int wid  = tid >> 5;
    const int tg   = wid * 2;
    const int h    = lane >> 4;          // half-warp id
    const int ln   = lane & 15;

    __shared__ float wpad[TT][32];       // 16 taps, 8-padded both sides
    __shared__ float xs[SROWS * 64];     // staged x rows (14 KB)
    __shared__ float rsum[8], rmn[8], rmx[8];

    const int   tl = tgt_lens[b];
    const float ls = ls_ptr[0];

    // ---- per-block mask reduce: sum + min/max (allones detection) ----
    {
        float part = 0.f, mn = 3.0e38f, mx = -3.0e38f;
        const int S4 = S >> 2;
        const float4* m4 = (const float4*)(mask + (size_t)b * S);
        for (int i = tid; i < S4; i += NTH_B) {
            float4 v = m4[i];
            part += (v.x + v.y) + (v.z + v.w);
            mn = fminf(mn, fminf(fminf(v.x, v.y), fminf(v.z, v.w)));
            mx = fmaxf(mx, fmaxf(fmaxf(v.x, v.y), fmaxf(v.z, v.w)));
        }
        for (int i = (S4 << 2) + tid; i < S; i += NTH_B) {
            float v = mask[(size_t)b * S + i];
            part += v; mn = fminf(mn, v); mx = fmaxf(mx, v);
        }
        #pragma unroll
        for (int o = 16; o > 0; o >>= 1) {
            part += __shfl_xor_sync(0xffffffffu, part, o);
            mn = fminf(mn, __shfl_xor_sync(0xffffffffu, mn, o));
            mx = fmaxf(mx, __shfl_xor_sync(0xffffffffu, mx, o));
        }
        if (lane == 0) { rsum[wid] = part; rmn[wid] = mn; rmx[wid] = mx; }
    }
    if (out_mask && tid < TT) {
        int t = t0 + tid;
        if (t < T) out_mask[(size_t)b * T + t] = (t < tl) ? 1.0f : 0.0f;
    }
    __syncthreads();

    float sl = 0.f, amn = 3.0e38f, amx = -3.0e38f;
    #pragma unroll
    for (int i = 0; i < 8; i++) {
        sl += rsum[i];
        amn = fminf(amn, rmn[i]);
        amx = fmaxf(amx, rmx[i]);
    }
    const float r  = sl / (float)tl;
    const float i2 = 1.0f / (2.0f * ls * ls);
    const bool  allones = (amn == 1.0f && amx == 1.0f);

    // ---- block-uniform stage window ----
    const int  tF  = min(t0, T - 1);
    const int  tL  = min(t0 + TT - 1, T - 1);
    const int  sbF = min(max(__float2int_rn(r * (float)tF) - 8, 0), S - W);
    const int  sbL = min(max(__float2int_rn(r * (float)tL) - 8, 0), S - W);
    const int  st0 = sbF;
    const bool blockfast = (sbL - sbF >= 0) && (sbL - sbF <= SROWS - 2 * NPAIRS);

    // ---- per-warp window bases (both t's, uniform ALU in every lane) ----
    const int   ta  = min(t0 + tg, T - 1);
    const int   tb  = min(t0 + tg + 1, T - 1);
    const float c0  = r * (float)ta;
    const float c1  = r * (float)tb;
    const int   s00 = __float2int_rn(c0);
    const int   s01 = __float2int_rn(c1);
    const int   sb0 = min(max(s00 - 8, 0), S - W);
    const int   sb1 = min(max(s01 - 8, 0), S - W);
    const int   delta = sb1 - sb0;

    // ---- stage via cp.async (issued as soon as r is known) ----
    if (blockfast) {
        const float4* xg4 = (const float4*)(x + ((size_t)b * S + st0) * 64);
        uint32_t xs_base = (uint32_t)__cvta_generic_to_shared(xs);
        const int avail = (S - st0) * 16;
        #pragma unroll
        for (int k = 0; k < 4; k++) {
            int idx = tid + k * NTH_B;
            if (idx < SVEC) {
                int nb   = (idx < avail) ? 16 : 0;
                int gidx = min(idx, avail - 1);
                cp_async16(xs_base + (uint32_t)idx * 16u, xg4 + gidx, nb);
            }
        }
        asm volatile("cp.async.commit_group;\n" ::: "memory");
    }

    // ---- half-warp softmax: lanes 0-15 -> t_a, 16-31 -> t_b ----
    {
        // zero this warp's 2 padded weight rows (2*32 floats = 16 float4)
        float4* wz = (float4*)&wpad[tg][0];
        if (lane < 16) wz[lane] = make_float4(0.f, 0.f, 0.f, 0.f);
        __syncwarp();

        const float ch  = h ? c1 : c0;
        const int   s0h = h ? s01 : s00;
        const int   sbh = h ? sb1 : sb0;
        float mv = 1.0f;
        if (!allones) mv = mask[(size_t)b * S + sbh + ln];
        const int   sn = min(max(s0h, 0), S - 1);
        const float dm = (float)sn - ch;
        const float M  = -dm * dm * i2;
        const float d  = (float)(sbh + ln) - ch;
        float lg = allones ? (-d * d * i2)
                           : (mv * (-d * d * i2) - (1.0f - mv) * 1e10f);
        float e  = __expf(lg - M);
        float sm = e;
        #pragma unroll
        for (int o = 8; o > 0; o >>= 1)
            sm += __shfl_xor_sync(0xffffffffu, sm, o);
        wpad[tg + h][8 + ln] = e * __fdividef(1.0f, sm);
    }

    if (blockfast) asm volatile("cp.async.wait_group 0;\n" ::: "memory");
    __syncthreads();

    float4 a0 = {0.f, 0.f, 0.f, 0.f};
    float4 a1 = {0.f, 0.f, 0.f, 0.f};

    if (blockfast && delta >= 0 && delta <= 4) {
        // union sweep from smem: lane covers row 2k+h, D-chunk ln
        const float4* __restrict__ xw4 = ((const float4*)xs) + (sb0 - st0) * 16;
        const float*  __restrict__ w0p = &wpad[tg + 0][8 + h];
        const float*  __restrict__ w1p = &wpad[tg + 1][8 - delta + h];
        #pragma unroll
        for (int k = 0; k < NPAIRS; k++) {
            float4 xv = xw4[k * 32 + lane];
            float  w0 = w0p[2 * k];
            float  w1 = w1p[2 * k];
            a0.x = fmaf(w0, xv.x, a0.x);  a0.y = fmaf(w0, xv.y, a0.y);
            a0.z = fmaf(w0, xv.z, a0.z);  a0.w = fmaf(w0, xv.w, a0.w);
            a1.x = fmaf(w1, xv.x, a1.x);  a1.y = fmaf(w1, xv.y, a1.y);
            a1.z = fmaf(w1, xv.z, a1.z);  a1.w = fmaf(w1, xv.w, a1.w);
        }
    } else {
        // exotic-r / boundary path: per-t independent W-row sweep from global
        const int sbs[2] = {sb0, sb1};
        #pragma unroll
        for (int tt = 0; tt < 2; tt++) {
            const float4* xt4 = (const float4*)(x + ((size_t)b * S + sbs[tt]) * 64);
            const float*  wp  = &wpad[tg + tt][8 + h];
            float4 acc = {0.f, 0.f, 0.f, 0.f};
            #pragma unroll
            for (int pr = 0; pr < W / 2; pr++) {
                float4 xv = xt4[pr * 32 + lane];
                float  w  = wp[pr * 2];
                acc.x = fmaf(w, xv.x, acc.x);  acc.y = fmaf(w, xv.y, acc.y);
                acc.z = fmaf(w, xv.z, acc.z);  acc.w = fmaf(w, xv.w, acc.w);
            }
            if (tt == 0) a0 = acc; else a1 = acc;
        }
    }

    // combine row-halves (butterfly leaves sum in both halves)
    a0.x += __shfl_xor_sync(0xffffffffu, a0.x, 16);
    a0.y += __shfl_xor_sync(0xffffffffu, a0.y, 16);
    a0.z += __shfl_xor_sync(0xffffffffu, a0.z, 16);
    a0.w += __shfl_xor_sync(0xffffffffu, a0.w, 16);
    a1.x += __shfl_xor_sync(0xffffffffu, a1.x, 16);
    a1.y += __shfl_xor_sync(0xffffffffu, a1.y, 16);
    a1.z += __shfl_xor_sync(0xffffffffu, a1.z, 16);
    a1.w += __shfl_xor_sync(0xffffffffu, a1.w, 16);

    // lanes 0-15 store t (tg+0), lanes 16-31 store t (tg+1): one STG.128
    int    tsel = t0 + tg + h;
    float4 av   = h ? a1 : a0;
    if (tsel < T) {
        float4* o4 = (float4*)(out_feat + ((size_t)b * T + tsel) * 64);
        o4[ln] = av;
    }
}

// Generic fallback (any D, any S>=32): one warp per (b,t).
__global__ void length_transform_generic(const float* __restrict__ x,
                                         const float* __restrict__ mask,
                                         const float* __restrict__ ls_ptr,
                                         const int*   __restrict__ tgt_lens,
                                         float* __restrict__ out_feat,
                                         float* __restrict__ out_mask,
                                         int B, int S, int T, int D)
{
    int bt = blockIdx.x;
    int b = bt / T, t = bt % T;
    int lane = threadIdx.x;
    __shared__ float wsh[32];

    float part = 0.f;
    for (int i = lane; i < S; i += 32) part += mask[(size_t)b * S + i];
    #pragma unroll
    for (int o = 16; o > 0; o >>= 1) part += __shfl_xor_sync(0xffffffffu, part, o);
    float sl = part;
    int   tl = tgt_lens[b];
    float r  = sl / (float)tl;
    float ls = ls_ptr[0];
    float i2 = 1.f / (2.f * ls * ls);

    float c  = r * (float)t;
    int   s0 = __float2int_rn(c);
    int   sb = min(max(s0 - 15, 0), max(S - 32, 0));
    int   s  = min(sb + lane, S - 1);
    float d  = (float)s - c;
    float lg0 = -d * d * i2;
    float m  = mask[(size_t)b * S + s];
    float lg = m * lg0 - (1.f - m) * 1e10f;
    if (sb + lane > S - 1) lg = -3.0e38f;
    float mx = lg;
    #pragma unroll
    for (int o = 16; o > 0; o >>= 1) mx = fmaxf(mx, __shfl_xor_sync(0xffffffffu, mx, o));
    float e = __expf(lg - mx);
    float sm = e;
    #pragma unroll
    for (int o = 16; o > 0; o >>= 1) sm += __shfl_xor_sync(0xffffffffu, sm, o);
    wsh[lane] = e / sm;
    __syncwarp();

    for (int dd = lane; dd < D; dd += 32) {
        float acc = 0.f;
        for (int k = 0; k < 32; k++) {
            int ss = sb + k;
            if (ss >= S) break;
            acc = fmaf(wsh[k], x[((size_t)b * S + ss) * D + dd], acc);
        }
        out_feat[((size_t)b * T + t) * D + dd] = acc;
    }
    if (out_mask && lane == 0) out_mask[(size_t)b * T + t] = (t < tl) ? 1.f : 0.f;
}

extern "C" void kernel_launch(void* const* d_in, const int* in_sizes, int n_in,
                              void* d_out, int out_size)
{
    const float* x     = (const float*)d_in[0];
    const float* mask  = (const float*)d_in[1];
    const float* ls    = (const float*)d_in[2];
    const int*   tlens = (const int*)d_in[3];

    const int BSD = in_sizes[0];
    const int BS  = in_sizes[1];
    const int B   = in_sizes[3];
    const int D   = BSD / BS;
    const int S   = BS / B;

    long fp1 = (long)B * (D + 1);
    int  T;
    bool has_mask;
    if (out_size % fp1 == 0) { T = (int)(out_size / fp1); has_mask = true; }
    else                     { T = (int)(out_size / ((long)B * D)); has_mask = false; }

    float* ofeat = (float*)d_out;
    float* omask = has_mask ? ofeat + (size_t)B * T * D : nullptr;

    if (D == 64 && S >= 64) {
        dim3 grid((T + TT - 1) / TT, B);
        lt_fused<<<grid, NTH_B>>>(x, mask, ls, tlens, ofeat, omask, B, S, T);
    } else {
        length_transform_generic<<<B * T, 32>>>(x, mask, ls, tlens, ofeat, omask, B, S, T, D);
    }
}